// round 1
// baseline (speedup 1.0000x reference)
#include <cuda_runtime.h>
#include <cuda_bf16.h>
#include <math.h>

#define H   2048
#define E   64
#define TOPK 4
#define SW  1024
#define Bsz 2
#define S   4096
#define NEGF (-3.402823466e+38f)
#define EPS 1e-6f
#define INV_SQRT_H 0.02209708691207961f   // 1/sqrt(2048)

// scratch for vision group ids
__device__ int g_gid[Bsz * S];

// ---------------------------------------------------------------------------
// Kernel 1: vision group ids (per-batch parallel scan over S)
// one block per batch row, 1024 threads x 4 items
// ---------------------------------------------------------------------------
__global__ void gid_kernel(const int* __restrict__ mm) {
    const int b = blockIdx.x;
    const int* m = mm + b * S;
    int* g = g_gid + b * S;
    const int t = threadIdx.x;
    const int base = t * 4;

    int isv[4], st[4];
    int cnt = 0;
#pragma unroll
    for (int i = 0; i < 4; i++) {
        int pos = base + i;
        int mv = m[pos];
        int v = (mv == 1 || mv == 2) ? 1 : 0;
        int pv = 0;
        if (pos > 0) {
            int pm = m[pos - 1];
            pv = (pm == 1 || pm == 2) ? 1 : 0;
        }
        int s = (v && !pv) ? 1 : 0;
        isv[i] = v; st[i] = s; cnt += s;
    }

    __shared__ int sh[1024];
    sh[t] = cnt;
    __syncthreads();
    // Hillis-Steele inclusive scan over 1024 thread-counts
    for (int off = 1; off < 1024; off <<= 1) {
        int v = (t >= off) ? sh[t - off] : 0;
        __syncthreads();
        sh[t] += v;
        __syncthreads();
    }
    int run = (t > 0) ? sh[t - 1] : 0;   // exclusive prefix
#pragma unroll
    for (int i = 0; i < 4; i++) {
        run += st[i];
        g[base + i] = isv[i] ? (run - 1) : -1;
    }
}

// ---------------------------------------------------------------------------
// Kernel 2: both additive masks. grid = (S, B), 256 threads.
// Each thread writes 4 x float4 per mask (vectorized streaming stores).
// ---------------------------------------------------------------------------
__global__ void __launch_bounds__(256) mask_kernel(const int* __restrict__ packed,
                                                   float* __restrict__ full_out,
                                                   float* __restrict__ slid_out) {
    const int q = blockIdx.x;
    const int b = blockIdx.y;
    const int pq = __ldg(&packed[b * S + q]);
    const int gq = g_gid[b * S + q];
    const bool validq = pq > 0;

    const size_t rowoff = ((size_t)b * S + (size_t)q) * (size_t)S;
    float4* fo = (float4*)(full_out + rowoff);
    float4* so = (float4*)(slid_out + rowoff);
    const int4* pr = (const int4*)(packed + b * S);
    const int4* gr = (const int4*)(g_gid + b * S);

    for (int c = threadIdx.x; c < S / 4; c += 256) {
        int4 pk = pr[c];
        int4 gk = gr[c];
        const int kv0 = c * 4;
        float4 f, sl;

        {
            bool sd = validq && (pk.x == pq);
            bool fu = sd && (kv0 + 0 <= q);
            bool sw = fu && ((q - (kv0 + 0)) < SW);
            bool vg = (gq >= 0) && (gk.x == gq);
            bool s2 = (sw || vg) && sd;
            f.x = fu ? 0.0f : NEGF;  sl.x = s2 ? 0.0f : NEGF;
        }
        {
            bool sd = validq && (pk.y == pq);
            bool fu = sd && (kv0 + 1 <= q);
            bool sw = fu && ((q - (kv0 + 1)) < SW);
            bool vg = (gq >= 0) && (gk.y == gq);
            bool s2 = (sw || vg) && sd;
            f.y = fu ? 0.0f : NEGF;  sl.y = s2 ? 0.0f : NEGF;
        }
        {
            bool sd = validq && (pk.z == pq);
            bool fu = sd && (kv0 + 2 <= q);
            bool sw = fu && ((q - (kv0 + 2)) < SW);
            bool vg = (gq >= 0) && (gk.z == gq);
            bool s2 = (sw || vg) && sd;
            f.z = fu ? 0.0f : NEGF;  sl.z = s2 ? 0.0f : NEGF;
        }
        {
            bool sd = validq && (pk.w == pq);
            bool fu = sd && (kv0 + 3 <= q);
            bool sw = fu && ((q - (kv0 + 3)) < SW);
            bool vg = (gq >= 0) && (gk.w == gq);
            bool s2 = (sw || vg) && sd;
            f.w = fu ? 0.0f : NEGF;  sl.w = s2 ? 0.0f : NEGF;
        }
        fo[c] = f;
        so[c] = sl;
    }
}

// ---------------------------------------------------------------------------
// Kernel 3: gate. One block per token (8192 blocks, 256 threads).
// RMSNorm -> scale -> 64 dot products -> softmax -> top-4 -> renorm.
// ---------------------------------------------------------------------------
__global__ void __launch_bounds__(256) gate_kernel(const float* __restrict__ x,
                                                   const float* __restrict__ scale,
                                                   const float* __restrict__ proj_w,
                                                   float* __restrict__ out_w,
                                                   float* __restrict__ out_i) {
    const int n = blockIdx.x;
    const float* xr = x + (size_t)n * H;

    __shared__ float sh_xn[H];
    __shared__ float sh_logits[E];
    __shared__ float sh_red[8];
    __shared__ float sh_total;

    const int tid = threadIdx.x;
    const int warp = tid >> 5;
    const int lane = tid & 31;

    // pass 1: load + sum of squares
    float ss = 0.0f;
    for (int h = tid; h < H; h += 256) {
        float v = xr[h];
        sh_xn[h] = v;
        ss += v * v;
    }
#pragma unroll
    for (int off = 16; off; off >>= 1) ss += __shfl_down_sync(0xffffffffu, ss, off);
    if (lane == 0) sh_red[warp] = ss;
    __syncthreads();
    if (warp == 0) {
        float v = (lane < 8) ? sh_red[lane] : 0.0f;
#pragma unroll
        for (int off = 4; off; off >>= 1) v += __shfl_down_sync(0xffffffffu, v, off);
        if (lane == 0) sh_total = v;
    }
    __syncthreads();

    const float factor = rsqrtf(sh_total * (1.0f / H) + EPS) * INV_SQRT_H;
    for (int h = tid; h < H; h += 256) {
        sh_xn[h] = sh_xn[h] * factor * scale[h];
    }
    __syncthreads();

    // logits: 8 warps, each warp handles experts warp, warp+8, ...
    for (int e = warp; e < E; e += 8) {
        const float* wr = proj_w + (size_t)e * H;
        float acc = 0.0f;
        for (int h = lane; h < H; h += 32) acc += sh_xn[h] * wr[h];
#pragma unroll
        for (int off = 16; off; off >>= 1) acc += __shfl_down_sync(0xffffffffu, acc, off);
        if (lane == 0) sh_logits[e] = acc;
    }
    __syncthreads();

    // thread 0: softmax numerators + top-4 (strict > -> lowest index wins ties,
    // matching jax.lax.top_k) + renormalize (softmax denominator cancels)
    if (tid == 0) {
        float mx = sh_logits[0];
#pragma unroll
        for (int e = 1; e < E; e++) mx = fmaxf(mx, sh_logits[e]);
        // overwrite with exp(l - mx)
        for (int e = 0; e < E; e++) sh_logits[e] = __expf(sh_logits[e] - mx);

        float wk[TOPK];
        int ik[TOPK];
        float psum = 0.0f;
#pragma unroll
        for (int k = 0; k < TOPK; k++) {
            float best = -1.0f;
            int bi = 0;
            for (int e = 0; e < E; e++) {
                float v = sh_logits[e];
                if (v > best) { best = v; bi = e; }
            }
            wk[k] = best; ik[k] = bi; psum += best;
            sh_logits[bi] = -2.0f;  // remove from candidates
        }
        float inv = 1.0f / fmaxf(psum, 1e-20f);
#pragma unroll
        for (int k = 0; k < TOPK; k++) {
            out_w[n * TOPK + k] = wk[k] * inv;
            out_i[n * TOPK + k] = (float)ik[k];
        }
    }
}

// ---------------------------------------------------------------------------
extern "C" void kernel_launch(void* const* d_in, const int* in_sizes, int n_in,
                              void* d_out, int out_size) {
    const float* x      = (const float*)d_in[0];   // [B,S,H]
    const int*   packed = (const int*)  d_in[1];   // [B,S]
    const int*   mm     = (const int*)  d_in[2];   // [B,S]
    const float* scale  = (const float*)d_in[3];   // [H]
    const float* proj_w = (const float*)d_in[4];   // [E,H]

    float* out = (float*)d_out;
    const size_t mask_elems = (size_t)Bsz * S * S;           // 33554432
    float* full_out = out;
    float* slid_out = out + mask_elems;
    float* wts_out  = out + 2 * mask_elems;
    float* idx_out  = wts_out + (size_t)Bsz * S * TOPK;

    gid_kernel<<<Bsz, 1024>>>(mm);
    mask_kernel<<<dim3(S, Bsz), 256>>>(packed, full_out, slid_out);
    gate_kernel<<<Bsz * S, 256>>>(x, scale, proj_w, wts_out, idx_out);
}

// round 2
// speedup vs baseline: 2.2048x; 2.2048x over previous
#include <cuda_runtime.h>
#include <cuda_bf16.h>
#include <math.h>

#define H    2048
#define E    64
#define TOPK 4
#define SW   1024
#define Bsz  2
#define S    4096
#define NEGF (-3.402823466e+38f)
#define EPS  1e-6f
#define INV_SQRT_H 0.02209708691207961f   // 1/sqrt(2048)

#define TM 64        // tokens per gate-GEMM block
#define KC 64        // K chunk
#define QT 32        // q rows per mask block

// scratch (__device__ globals: allocation-free)
__device__ int   g_gid[Bsz * S];
__device__ float g_factor[Bsz * S];
__device__ float g_wp[E * H];        // proj_w * scale * H^-0.5

// ---------------------------------------------------------------------------
// packed f32x2 FMA
// ---------------------------------------------------------------------------
__device__ __forceinline__ void fma_f32x2(unsigned long long& d,
                                          unsigned long long a,
                                          unsigned long long b) {
    asm("fma.rn.f32x2 %0, %1, %2, %0;" : "+l"(d) : "l"(a), "l"(b));
}

// ---------------------------------------------------------------------------
// Kernel 1: vision group ids — warp-shuffle scan (3 barriers)
// ---------------------------------------------------------------------------
__global__ void __launch_bounds__(1024) gid_kernel(const int* __restrict__ mm) {
    const int b = blockIdx.x;
    const int* m = mm + b * S;
    int* g = g_gid + b * S;
    const int t = threadIdx.x;
    const int lane = t & 31, warp = t >> 5;
    const int base = t * 4;

    int isv[4], st[4];
    int cnt = 0;
#pragma unroll
    for (int i = 0; i < 4; i++) {
        int pos = base + i;
        int mv = m[pos];
        int v = (mv == 1 || mv == 2) ? 1 : 0;
        int pv = 0;
        if (pos > 0) {
            int pm = m[pos - 1];
            pv = (pm == 1 || pm == 2) ? 1 : 0;
        }
        int s = (v && !pv) ? 1 : 0;
        isv[i] = v; st[i] = s; cnt += s;
    }

    // warp inclusive scan of cnt
    int inc = cnt;
#pragma unroll
    for (int off = 1; off < 32; off <<= 1) {
        int v = __shfl_up_sync(0xffffffffu, inc, off);
        if (lane >= off) inc += v;
    }
    __shared__ int wsum[32];
    if (lane == 31) wsum[warp] = inc;
    __syncthreads();
    if (warp == 0) {
        int v = wsum[lane];
#pragma unroll
        for (int off = 1; off < 32; off <<= 1) {
            int u = __shfl_up_sync(0xffffffffu, v, off);
            if (lane >= off) v += u;
        }
        wsum[lane] = v;   // inclusive warp sums
    }
    __syncthreads();
    int run = ((warp > 0) ? wsum[warp - 1] : 0) + inc - cnt;  // exclusive prefix
#pragma unroll
    for (int i = 0; i < 4; i++) {
        run += st[i];
        g[base + i] = isv[i] ? (run - 1) : -1;
    }
}

// ---------------------------------------------------------------------------
// Kernel 2: masks. grid = (S/QT, B). packed/gid rows cached in smem once,
// amortized over QT q-rows  -> pure DRAM-write-bound.
// ---------------------------------------------------------------------------
__global__ void __launch_bounds__(256) mask_kernel(const int* __restrict__ packed,
                                                   float* __restrict__ full_out,
                                                   float* __restrict__ slid_out) {
    const int b = blockIdx.y;
    __shared__ int sp[S];
    __shared__ int sg[S];
    {
        const int4* pr = (const int4*)(packed + b * S);
        const int4* gr = (const int4*)(g_gid + b * S);
        for (int i = threadIdx.x; i < S / 4; i += 256) {
            ((int4*)sp)[i] = pr[i];
            ((int4*)sg)[i] = gr[i];
        }
    }
    __syncthreads();

    const int q0 = blockIdx.x * QT;
    for (int qi = 0; qi < QT; qi++) {
        const int q = q0 + qi;
        const int pq = sp[q];
        const int gq = sg[q];
        const bool validq = pq > 0;
        const size_t rowoff = ((size_t)b * S + (size_t)q) * (size_t)S;
        float4* fo = (float4*)(full_out + rowoff);
        float4* so = (float4*)(slid_out + rowoff);

        for (int c = threadIdx.x; c < S / 4; c += 256) {
            int4 pk = ((const int4*)sp)[c];
            int4 gk = ((const int4*)sg)[c];
            const int kv0 = c * 4;
            float4 f, sl;
            {
                bool sd = validq && (pk.x == pq);
                bool fu = sd && (kv0 + 0 <= q);
                bool sw = fu && ((q - (kv0 + 0)) < SW);
                bool vg = (gq >= 0) && (gk.x == gq);
                bool s2 = (sw || vg) && sd;
                f.x = fu ? 0.0f : NEGF;  sl.x = s2 ? 0.0f : NEGF;
            }
            {
                bool sd = validq && (pk.y == pq);
                bool fu = sd && (kv0 + 1 <= q);
                bool sw = fu && ((q - (kv0 + 1)) < SW);
                bool vg = (gq >= 0) && (gk.y == gq);
                bool s2 = (sw || vg) && sd;
                f.y = fu ? 0.0f : NEGF;  sl.y = s2 ? 0.0f : NEGF;
            }
            {
                bool sd = validq && (pk.z == pq);
                bool fu = sd && (kv0 + 2 <= q);
                bool sw = fu && ((q - (kv0 + 2)) < SW);
                bool vg = (gq >= 0) && (gk.z == gq);
                bool s2 = (sw || vg) && sd;
                f.z = fu ? 0.0f : NEGF;  sl.z = s2 ? 0.0f : NEGF;
            }
            {
                bool sd = validq && (pk.w == pq);
                bool fu = sd && (kv0 + 3 <= q);
                bool sw = fu && ((q - (kv0 + 3)) < SW);
                bool vg = (gq >= 0) && (gk.w == gq);
                bool s2 = (sw || vg) && sd;
                f.w = fu ? 0.0f : NEGF;  sl.w = s2 ? 0.0f : NEGF;
            }
            fo[c] = f;
            so[c] = sl;
        }
    }
}

// ---------------------------------------------------------------------------
// Kernel 3: per-token rsqrt factor. One warp per token.
// ---------------------------------------------------------------------------
__global__ void __launch_bounds__(256) rms_kernel(const float* __restrict__ x) {
    const int warp = threadIdx.x >> 5;
    const int lane = threadIdx.x & 31;
    const int n = blockIdx.x * 8 + warp;
    const float4* xr = (const float4*)(x + (size_t)n * H);
    float ss = 0.0f;
#pragma unroll
    for (int j = 0; j < 16; j++) {
        float4 v = xr[lane + j * 32];
        ss += v.x * v.x + v.y * v.y + v.z * v.z + v.w * v.w;
    }
#pragma unroll
    for (int off = 16; off; off >>= 1) ss += __shfl_down_sync(0xffffffffu, ss, off);
    if (lane == 0) g_factor[n] = rsqrtf(ss * (1.0f / H) + EPS);
}

// ---------------------------------------------------------------------------
// Kernel 4: fold scale*H^-0.5 into proj_w
// ---------------------------------------------------------------------------
__global__ void __launch_bounds__(256) wp_kernel(const float* __restrict__ proj_w,
                                                 const float* __restrict__ scale) {
    int i = blockIdx.x * 256 + threadIdx.x;
    if (i < E * H) {
        g_wp[i] = proj_w[i] * scale[i & (H - 1)] * INV_SQRT_H;
    }
}

// ---------------------------------------------------------------------------
// Kernel 5: gate GEMM + softmax + top-4.
// Block: TM=64 tokens x 64 experts, 256 threads, 4x4 register tile, f32x2 FMA.
// ---------------------------------------------------------------------------
__global__ void __launch_bounds__(256) gate_gemm(const float* __restrict__ x,
                                                 float* __restrict__ out_w,
                                                 float* __restrict__ out_i) {
    const int n0 = blockIdx.x * TM;
    __shared__ float xs[TM][KC];       // 16 KB
    __shared__ float ws[E][KC + 2];    // padded rows -> conflict-free b2 loads
    __shared__ float lg[TM][E + 1];

    const int tid = threadIdx.x;
    const int tr = tid >> 4;   // 0..15 token group
    const int tc = tid & 15;   // 0..15 expert group

    unsigned long long acc[4][4];
#pragma unroll
    for (int i = 0; i < 4; i++)
#pragma unroll
        for (int j = 0; j < 4; j++) acc[i][j] = 0ull;

    for (int kb = 0; kb < H; kb += KC) {
#pragma unroll
        for (int i = 0; i < 8; i++) {
            int idx = tid + i * 256;           // float2 index
            int row = idx >> 5;                // / (KC/2)
            int col = idx & 31;
            float2 v = *(const float2*)(x + (size_t)(n0 + row) * H + kb + col * 2);
            *(float2*)&xs[row][col * 2] = v;
        }
#pragma unroll
        for (int i = 0; i < 8; i++) {
            int idx = tid + i * 256;
            int row = idx >> 5;
            int col = idx & 31;
            float2 v = *(const float2*)(g_wp + (size_t)row * H + kb + col * 2);
            *(float2*)&ws[row][col * 2] = v;
        }
        __syncthreads();

#pragma unroll 8
        for (int k2 = 0; k2 < KC / 2; k2++) {
            unsigned long long a2[4], b2[4];
#pragma unroll
            for (int i = 0; i < 4; i++)
                a2[i] = *(const unsigned long long*)&xs[tr + 16 * i][k2 * 2];
#pragma unroll
            for (int j = 0; j < 4; j++)
                b2[j] = *(const unsigned long long*)&ws[tc + 16 * j][k2 * 2];
#pragma unroll
            for (int i = 0; i < 4; i++)
#pragma unroll
                for (int j = 0; j < 4; j++)
                    fma_f32x2(acc[i][j], a2[i], b2[j]);
        }
        __syncthreads();
    }

    // write logits to smem
#pragma unroll
    for (int i = 0; i < 4; i++)
#pragma unroll
        for (int j = 0; j < 4; j++) {
            float2 p = *(float2*)&acc[i][j];
            lg[tr + 16 * i][tc + 16 * j] = p.x + p.y;
        }
    __syncthreads();

    // one thread per token: scale by rsqrt factor, top-4 (strict > => lowest
    // index on ties, matching jax.lax.top_k), renormalize (softmax denom cancels)
    if (tid < TM) {
        const int n = n0 + tid;
        const float f = g_factor[n];
        float l[E];
#pragma unroll
        for (int e = 0; e < E; e++) l[e] = lg[tid][e] * f;

        float wk[TOPK]; int ik[TOPK];
#pragma unroll
        for (int k = 0; k < TOPK; k++) {
            float best = -3.4e38f; int bi = 0;
            for (int e = 0; e < E; e++) {
                float v = l[e];
                if (v > best) { best = v; bi = e; }
            }
            wk[k] = best; ik[k] = bi;
            l[bi] = -3.4e38f;
        }
        const float m = wk[0];
        float p[TOPK], psum = 0.0f;
#pragma unroll
        for (int k = 0; k < TOPK; k++) { p[k] = __expf(wk[k] - m); psum += p[k]; }
        const float inv = 1.0f / fmaxf(psum, 1e-20f);
#pragma unroll
        for (int k = 0; k < TOPK; k++) {
            out_w[n * TOPK + k] = p[k] * inv;
            out_i[n * TOPK + k] = (float)ik[k];
        }
    }
}

// ---------------------------------------------------------------------------
extern "C" void kernel_launch(void* const* d_in, const int* in_sizes, int n_in,
                              void* d_out, int out_size) {
    const float* x      = (const float*)d_in[0];   // [B,S,H]
    const int*   packed = (const int*)  d_in[1];   // [B,S]
    const int*   mm     = (const int*)  d_in[2];   // [B,S]
    const float* scale  = (const float*)d_in[3];   // [H]
    const float* proj_w = (const float*)d_in[4];   // [E,H]

    float* out = (float*)d_out;
    const size_t mask_elems = (size_t)Bsz * S * S;           // 33554432
    float* full_out = out;
    float* slid_out = out + mask_elems;
    float* wts_out  = out + 2 * mask_elems;
    float* idx_out  = wts_out + (size_t)Bsz * S * TOPK;

    gid_kernel<<<Bsz, 1024>>>(mm);
    rms_kernel<<<(Bsz * S) / 8, 256>>>(x);
    wp_kernel<<<(E * H + 255) / 256, 256>>>(proj_w, scale);
    mask_kernel<<<dim3(S / QT, Bsz), 256>>>(packed, full_out, slid_out);
    gate_gemm<<<(Bsz * S) / TM, 256>>>(x, wts_out, idx_out);
}

// round 4
// speedup vs baseline: 3.1817x; 1.4431x over previous
#include <cuda_runtime.h>
#include <cuda_bf16.h>
#include <math.h>

#define H    2048
#define E    64
#define TOPK 4
#define SW   1024
#define Bsz  2
#define S    4096
#define NEGF (-3.402823466e+38f)
#define EPS  1e-6f
#define INV_SQRT_H 0.02209708691207961f   // 1/sqrt(2048)

#define NTOK   (Bsz * S)          // 8192 tokens
#define KSPLIT 4
#define KSEG   (H / KSPLIT)       // 512
#define KC     32                 // k chunk per smem stage
#define TMB    256                // tokens per gemm block
#define XSTR   36                 // padded smem row stride (floats)

typedef unsigned long long ull;

// scratch (__device__ globals: allocation-free)
__device__ int   g_gid[Bsz * S];
__device__ int   g_vstart[Bsz * S];
__device__ int   g_vend[Bsz * S];
__device__ int   g_dstart[Bsz * 8];
__device__ int   g_dend[Bsz * 8];
__device__ float g_wp[E * H];                  // proj_w * scale * H^-0.5
__device__ float g_plog[KSPLIT * NTOK * E];    // partial logits (8 MB)
__device__ float g_ss[KSPLIT * NTOK];          // partial sum-of-squares

__device__ __forceinline__ void fma_f32x2(ull& d, ull a, ull b) {
    asm("fma.rn.f32x2 %0, %1, %2, %0;" : "+l"(d) : "l"(a), "l"(b));
}

// ---------------------------------------------------------------------------
// Kernel 1: vision group ids + doc/vision interval endpoints
// ---------------------------------------------------------------------------
__global__ void __launch_bounds__(1024) gid_kernel(const int* __restrict__ mm,
                                                   const int* __restrict__ packed) {
    const int b = blockIdx.x;
    const int* m = mm + b * S;
    const int* p = packed + b * S;
    int* g = g_gid + b * S;
    const int t = threadIdx.x;
    const int lane = t & 31, warp = t >> 5;
    const int base = t * 4;

    int isv[5], st[4];
    int cnt = 0;
#pragma unroll
    for (int i = 0; i < 4; i++) {
        int pos = base + i;
        int mv = m[pos];
        int v = (mv == 1 || mv == 2) ? 1 : 0;
        int pv = 0;
        if (pos > 0) {
            int pm = m[pos - 1];
            pv = (pm == 1 || pm == 2) ? 1 : 0;
        }
        int s = (v && !pv) ? 1 : 0;
        isv[i] = v; st[i] = s; cnt += s;
    }
    // next-token vision flag for end detection
    {
        int pos = base + 4;
        int nv = 0;
        if (pos < S) {
            int nm = m[pos];
            nv = (nm == 1 || nm == 2) ? 1 : 0;
        }
        isv[4] = nv;
    }

    // doc interval endpoints (packed is sorted per row, ids 0..4)
#pragma unroll
    for (int i = 0; i < 4; i++) {
        int pos = base + i;
        int v = p[pos];
        int prev = (pos > 0) ? p[pos - 1] : -1;
        int next = (pos < S - 1) ? p[pos + 1] : -1;
        if (v != prev && v >= 0 && v < 8) g_dstart[b * 8 + v] = pos;
        if (v != next && v >= 0 && v < 8) g_dend[b * 8 + v] = pos;
    }

    // warp inclusive scan of cnt
    int inc = cnt;
#pragma unroll
    for (int off = 1; off < 32; off <<= 1) {
        int v = __shfl_up_sync(0xffffffffu, inc, off);
        if (lane >= off) inc += v;
    }
    __shared__ int wsum[32];
    if (lane == 31) wsum[warp] = inc;
    __syncthreads();
    if (warp == 0) {
        int v = wsum[lane];
#pragma unroll
        for (int off = 1; off < 32; off <<= 1) {
            int u = __shfl_up_sync(0xffffffffu, v, off);
            if (lane >= off) v += u;
        }
        wsum[lane] = v;
    }
    __syncthreads();
    int run = ((warp > 0) ? wsum[warp - 1] : 0) + inc - cnt;  // exclusive prefix
#pragma unroll
    for (int i = 0; i < 4; i++) {
        run += st[i];
        int pos = base + i;
        int gv = isv[i] ? (run - 1) : -1;
        g[pos] = gv;
        if (gv >= 0) {
            if (st[i]) g_vstart[b * S + gv] = pos;
            if (!isv[i + 1] || pos == S - 1) g_vend[b * S + gv] = pos;
        }
    }
}

// ---------------------------------------------------------------------------
// Kernel 2: masks as interval fills. grid = (S, B), 256 threads.
// No smem, 2-6 compares per element, pure streaming stores.
// ---------------------------------------------------------------------------
__global__ void __launch_bounds__(256) mask_kernel(const int* __restrict__ packed,
                                                   float* __restrict__ full_out,
                                                   float* __restrict__ slid_out) {
    const int q = blockIdx.x;
    const int b = blockIdx.y;
    const int pq = __ldg(&packed[b * S + q]);

    int flo = 1, fhi = 0;     // full zero-interval
    int alo = 1, ahi = 0;     // sliding causal interval
    int clo = 1, chi = 0;     // vision interval
    if (pq > 0) {
        const int dlo = g_dstart[b * 8 + pq];
        const int dhi = g_dend[b * 8 + pq];
        flo = dlo; fhi = q;
        alo = max(dlo, q - SW + 1); ahi = q;
        const int gq = g_gid[b * S + q];
        if (gq >= 0) {
            clo = max(g_vstart[b * S + gq], dlo);
            chi = min(g_vend[b * S + gq], dhi);
        }
    }

    const size_t rowoff = ((size_t)b * S + (size_t)q) * (size_t)S;
    float4* fo = (float4*)(full_out + rowoff);
    float4* so = (float4*)(slid_out + rowoff);

#pragma unroll
    for (int it = 0; it < 4; it++) {
        const int c = threadIdx.x + it * 256;
        const int kv = c * 4;
        float4 f, sl;
        f.x = (kv + 0 >= flo && kv + 0 <= fhi) ? 0.0f : NEGF;
        f.y = (kv + 1 >= flo && kv + 1 <= fhi) ? 0.0f : NEGF;
        f.z = (kv + 2 >= flo && kv + 2 <= fhi) ? 0.0f : NEGF;
        f.w = (kv + 3 >= flo && kv + 3 <= fhi) ? 0.0f : NEGF;
        sl.x = ((kv + 0 >= alo && kv + 0 <= ahi) || (kv + 0 >= clo && kv + 0 <= chi)) ? 0.0f : NEGF;
        sl.y = ((kv + 1 >= alo && kv + 1 <= ahi) || (kv + 1 >= clo && kv + 1 <= chi)) ? 0.0f : NEGF;
        sl.z = ((kv + 2 >= alo && kv + 2 <= ahi) || (kv + 2 >= clo && kv + 2 <= chi)) ? 0.0f : NEGF;
        sl.w = ((kv + 3 >= alo && kv + 3 <= ahi) || (kv + 3 >= clo && kv + 3 <= chi)) ? 0.0f : NEGF;
        __stcs(&fo[c], f);
        __stcs(&so[c], sl);
    }
}

// ---------------------------------------------------------------------------
// Kernel 3: fold scale*H^-0.5 into proj_w
// ---------------------------------------------------------------------------
__global__ void __launch_bounds__(256) wp_kernel(const float* __restrict__ proj_w,
                                                 const float* __restrict__ scale) {
    int i = blockIdx.x * 256 + threadIdx.x;
    if (i < E * H) {
        g_wp[i] = proj_w[i] * scale[i & (H - 1)] * INV_SQRT_H;
    }
}

// ---------------------------------------------------------------------------
// Kernel 4: gate GEMM, split-K. grid = (NTOK/TMB, KSPLIT) = (32, 4).
// Block: 256 tokens x 64 experts over K=512. 256 threads, 8x8 thread tile,
// f32x2 FMA (ratio 4 FFMA2 : 1 LDS.64). Also accumulates sum-of-squares of x.
// ---------------------------------------------------------------------------
__global__ void __launch_bounds__(256) gate_gemm(const float* __restrict__ x) {
    const int n0 = blockIdx.x * TMB;
    const int ks = blockIdx.y;
    const int kb0 = ks * KSEG;

    __shared__ float xs[TMB * XSTR];   // 36 KB
    __shared__ float ws[E * XSTR];     // 9 KB (reused for ss reduce)

    const int tid = threadIdx.x;
    const int tr = tid >> 3;    // 0..31 token group
    const int tc = tid & 7;     // 0..7 expert group

    ull acc[8][8];
#pragma unroll
    for (int i = 0; i < 8; i++)
#pragma unroll
        for (int j = 0; j < 8; j++) acc[i][j] = 0ull;
    float ssp[8];
#pragma unroll
    for (int j = 0; j < 8; j++) ssp[j] = 0.0f;

    for (int stage = 0; stage < KSEG / KC; stage++) {
        const int kb = kb0 + stage * KC;
        // load x tile: 256 rows x 32 floats
#pragma unroll
        for (int j = 0; j < 8; j++) {
            int idx = tid + j * 256;
            int row = idx >> 3;
            int col = idx & 7;
            float4 v = *(const float4*)(x + (size_t)(n0 + row) * H + kb + col * 4);
            *(float4*)&xs[row * XSTR + col * 4] = v;
            ssp[j] += v.x * v.x + v.y * v.y + v.z * v.z + v.w * v.w;
        }
        // load w tile: 64 rows x 32 floats
#pragma unroll
        for (int j = 0; j < 2; j++) {
            int idx = tid + j * 256;
            int row = idx >> 3;
            int col = idx & 7;
            float4 v = *(const float4*)(g_wp + (size_t)row * H + kb + col * 4);
            *(float4*)&ws[row * XSTR + col * 4] = v;
        }
        __syncthreads();

#pragma unroll
        for (int k2 = 0; k2 < KC / 2; k2++) {
            ull a2[8], b2[8];
#pragma unroll
            for (int i = 0; i < 8; i++)
                a2[i] = *(const ull*)&xs[(tr + 32 * i) * XSTR + k2 * 2];
#pragma unroll
            for (int j = 0; j < 8; j++)
                b2[j] = *(const ull*)&ws[(tc + 8 * j) * XSTR + k2 * 2];
#pragma unroll
            for (int i = 0; i < 8; i++)
#pragma unroll
                for (int j = 0; j < 8; j++)
                    fma_f32x2(acc[i][j], a2[i], b2[j]);
        }
        __syncthreads();
    }

    // sum-of-squares reduce: token rows (tid>>3)+32j got ssp[j] from this thread;
    // 8 threads (tid&7 = 0..7) share each row.
    float* ssm = ws;   // reuse (needs 8 KB)
#pragma unroll
    for (int j = 0; j < 8; j++) ssm[j * 256 + tid] = ssp[j];
    __syncthreads();
    {
        // token row = tid: j = tid>>5, r0 = tid&31, contributors tid' = r0*8+u
        float s = 0.0f;
        const int jj = tid >> 5;
        const int r0 = tid & 31;
#pragma unroll
        for (int u = 0; u < 8; u++) s += ssm[jj * 256 + r0 * 8 + u];
        g_ss[ks * NTOK + n0 + tid] = s;
    }

    // write partial logits
#pragma unroll
    for (int i = 0; i < 8; i++) {
        const int n = n0 + tr + 32 * i;
#pragma unroll
        for (int j = 0; j < 8; j++) {
            float2 p = *(float2*)&acc[i][j];
            g_plog[(size_t)ks * NTOK * E + (size_t)n * E + tc + 8 * j] = p.x + p.y;
        }
    }
}

// ---------------------------------------------------------------------------
// Kernel 5: reduce split-K partials, apply rms factor, softmax + top-4.
// grid = NTOK/64 = 128 blocks, 256 threads.
// ---------------------------------------------------------------------------
__global__ void __launch_bounds__(256) gate_final(float* __restrict__ out_w,
                                                  float* __restrict__ out_i) {
    const int t0 = blockIdx.x * 64;
    __shared__ float lg[64][E + 1];
    const int tid = threadIdx.x;

#pragma unroll
    for (int m = 0; m < 16; m++) {
        int eidx = tid + m * 256;        // 0..4095
        int tok = eidx >> 6;
        int e = eidx & 63;
        float s = 0.0f;
#pragma unroll
        for (int ks = 0; ks < KSPLIT; ks++)
            s += g_plog[(size_t)ks * NTOK * E + (size_t)(t0 + tok) * E + e];
        lg[tok][e] = s;
    }
    __syncthreads();

    if (tid < 64) {
        const int n = t0 + tid;
        float ss = 0.0f;
#pragma unroll
        for (int ks = 0; ks < KSPLIT; ks++) ss += g_ss[ks * NTOK + n];
        const float f = rsqrtf(ss * (1.0f / H) + EPS);

        float l[E];
#pragma unroll
        for (int e = 0; e < E; e++) l[e] = lg[tid][e] * f;

        float wk[TOPK]; int ik[TOPK];
#pragma unroll
        for (int k = 0; k < TOPK; k++) {
            float best = -3.4e38f; int bi = 0;
            for (int e = 0; e < E; e++) {
                float v = l[e];
                if (v > best) { best = v; bi = e; }
            }
            wk[k] = best; ik[k] = bi;
            l[bi] = -3.4e38f;
        }
        const float m = wk[0];
        float p[TOPK], psum = 0.0f;
#pragma unroll
        for (int k = 0; k < TOPK; k++) { p[k] = __expf(wk[k] - m); psum += p[k]; }
        const float inv = 1.0f / fmaxf(psum, 1e-20f);
#pragma unroll
        for (int k = 0; k < TOPK; k++) {
            out_w[n * TOPK + k] = p[k] * inv;
            out_i[n * TOPK + k] = (float)ik[k];
        }
    }
}

// ---------------------------------------------------------------------------
extern "C" void kernel_launch(void* const* d_in, const int* in_sizes, int n_in,
                              void* d_out, int out_size) {
    const float* x      = (const float*)d_in[0];   // [B,S,H]
    const int*   packed = (const int*)  d_in[1];   // [B,S]
    const int*   mm     = (const int*)  d_in[2];   // [B,S]
    const float* scale  = (const float*)d_in[3];   // [H]
    const float* proj_w = (const float*)d_in[4];   // [E,H]

    float* out = (float*)d_out;
    const size_t mask_elems = (size_t)Bsz * S * S;           // 33554432
    float* full_out = out;
    float* slid_out = out + mask_elems;
    float* wts_out  = out + 2 * mask_elems;
    float* idx_out  = wts_out + (size_t)NTOK * TOPK;

    gid_kernel<<<Bsz, 1024>>>(mm, packed);
    wp_kernel<<<(E * H + 255) / 256, 256>>>(proj_w, scale);
    gate_gemm<<<dim3(NTOK / TMB, KSPLIT), 256>>>(x);
    gate_final<<<NTOK / 64, 256>>>(wts_out, idx_out);
    mask_kernel<<<dim3(S, Bsz), 256>>>(packed, full_out, slid_out);
}